// round 15
// baseline (speedup 1.0000x reference)
#include <cuda_runtime.h>
#include <cuda_bf16.h>
#include <cstdint>

#define NHN 50000
#define NON 50000
#define NMP 50048   // padded rows (391 * 128)
#define NE  500000
#define DIM 256
#define NL  8
#define NB  512
#define NC  117

// ---------------- device scratch (no allocations allowed) ----------------
__device__ float g_hs0[NHN * DIM];
__device__ float g_hs1[NON * DIM];
__device__ float g_as[2][2][NHN];   // [layer parity][rel]
__device__ float g_ad[2][2][NHN];   // [layer parity][rel]
__device__ float g_uv[4][NL * DIM];
__device__ float g_c[2 * NL * 2];

// bf16 hi/lo split node features (padded to NMP rows, zero-init pad).
// These ARE the node state; fp32 value = hi + lo (error ~2^-18).
__device__ __nv_bfloat16 g_xhh[NMP * DIM];
__device__ __nv_bfloat16 g_xhl[NMP * DIM];
__device__ __nv_bfloat16 g_xoh[NMP * DIM];
__device__ __nv_bfloat16 g_xol[NMP * DIM];

// W^T split: [rel*NL+l][n][k] bf16
__device__ __nv_bfloat16 g_Bh[2 * NL * DIM * DIM];
__device__ __nv_bfloat16 g_Bl[2 * NL * DIM * DIM];

__device__ int    g_cnt[2][NHN];
__device__ int    g_rowptr[2][NHN + 1];
__device__ int    g_pos[2][NHN];
__device__ int    g_srcP[2][NE];
__device__ float2 g_eaP[2][NE];

__device__ float g_hpool[NB * DIM];
__device__ float g_opool[NB * DIM];
__device__ float g_epool[NB * 32];
__device__ int   g_cnth[NB];
__device__ int   g_cnto[NB];
__device__ int   g_cnte[NB];

// ================= portable PTX helpers (sm_80+ features only) =============
__device__ __forceinline__ uint32_t smem_u32(const void* p) {
    uint32_t a;
    asm("{ .reg .u64 t; cvta.to.shared.u64 t, %1; cvt.u32.u64 %0, t; }"
        : "=r"(a) : "l"(p));
    return a;
}

__device__ __forceinline__ void cp16(uint32_t s, const void* g) {
    asm volatile("cp.async.cg.shared.global [%0], [%1], 16;" :: "r"(s), "l"(g) : "memory");
}

__device__ __forceinline__ void ldm4(uint32_t* r, uint32_t addr) {
    asm volatile("ldmatrix.sync.aligned.m8n8.x4.shared.b16 {%0,%1,%2,%3}, [%4];"
                 : "=r"(r[0]), "=r"(r[1]), "=r"(r[2]), "=r"(r[3]) : "r"(addr));
}

__device__ __forceinline__ void mma16816(float* c, const uint32_t* a, const uint32_t* b) {
    asm volatile(
        "mma.sync.aligned.m16n8k16.row.col.f32.bf16.bf16.f32 "
        "{%0,%1,%2,%3}, {%4,%5,%6,%7}, {%8,%9}, {%0,%1,%2,%3};"
        : "+f"(c[0]), "+f"(c[1]), "+f"(c[2]), "+f"(c[3])
        : "r"(a[0]), "r"(a[1]), "r"(a[2]), "r"(a[3]), "r"(b[0]), "r"(b[1]));
}

// ---------------- small kernels ----------------

__global__ void k_copy_x(const float* __restrict__ xh, const float* __restrict__ xo) {
    int i = blockIdx.x * blockDim.x + threadIdx.x;
    if (i < NHN * DIM) {
        float v = xh[i];
        __nv_bfloat16 h = __float2bfloat16(v);
        g_xhh[i] = h;
        g_xhl[i] = __float2bfloat16(v - __bfloat162float(h));
    }
    if (i < NON * DIM) {
        float v = xo[i];
        __nv_bfloat16 h = __float2bfloat16(v);
        g_xoh[i] = h;
        g_xol[i] = __float2bfloat16(v - __bfloat162float(h));
    }
}

// all four uv vectors in one launch; which = blockIdx.y
__global__ void k_matrow4(const float* __restrict__ W0, const float* __restrict__ a0,
                          const float* __restrict__ W1, const float* __restrict__ a1,
                          const float* __restrict__ W2, const float* __restrict__ a2,
                          const float* __restrict__ W3, const float* __restrict__ a3) {
    int which = blockIdx.y;
    const float* W = which == 0 ? W0 : which == 1 ? W1 : which == 2 ? W2 : W3;
    const float* a = which == 0 ? a0 : which == 1 ? a1 : which == 2 ? a2 : a3;
    int g = (blockIdx.x * blockDim.x + threadIdx.x) >> 5;
    if (g >= NL * DIM) return;
    int lane = threadIdx.x & 31;
    int l = g >> 8, i = g & 255;
    const float* wr = W + (size_t)l * DIM * DIM + (size_t)i * DIM;
    const float* ar = a + l * DIM;
    float s = 0.f;
    for (int j = lane; j < DIM; j += 32) s += wr[j] * ar[j];
#pragma unroll
    for (int off = 16; off > 0; off >>= 1) s += __shfl_down_sync(0xffffffffu, s, off);
    if (lane == 0) g_uv[which][g] = s;
}

// both relations' edge coefficients; rel = blockIdx.x
__global__ void k_cdot2(const float* __restrict__ We0, const float* __restrict__ ae0,
                        const float* __restrict__ We1, const float* __restrict__ ae1) {
    int rel = blockIdx.x;
    const float* We = rel ? We1 : We0;
    const float* ae = rel ? ae1 : ae0;
    int idx = threadIdx.x;
    if (idx >= NL * 2) return;
    int l = idx >> 1, k = idx & 1;
    const float* wr = We + (size_t)l * 2 * DIM + (size_t)k * DIM;
    const float* ar = ae + l * DIM;
    float s = 0.f;
    for (int j = 0; j < DIM; j++) s += wr[j] * ar[j];
    g_c[rel * NL * 2 + l * 2 + k] = s;
}

// W[l][k][n] -> Bh/Bl[(rel*NL+l)][n][k] (transpose + hi/lo split)
__global__ void k_prepW(const float* __restrict__ Wh, const float* __restrict__ Wo) {
    int idx = blockIdx.x * blockDim.x + threadIdx.x;
    if (idx >= 2 * NL * DIM * DIM) return;
    int rel = idx / (NL * DIM * DIM);
    int r = idx % (NL * DIM * DIM);
    int l = r / (DIM * DIM);
    int kk = (r / DIM) % DIM;
    int n = r % DIM;
    const float* W = rel ? Wo : Wh;
    float w = W[(size_t)l * DIM * DIM + (size_t)kk * DIM + n];
    __nv_bfloat16 hi = __float2bfloat16(w);
    __nv_bfloat16 lo = __float2bfloat16(w - __bfloat162float(hi));
    size_t dst = ((size_t)(rel * NL + l) * DIM + n) * DIM + kk;
    g_Bh[dst] = hi;
    g_Bl[dst] = lo;
}

__global__ void k_zero_csr() {
    int i = blockIdx.x * blockDim.x + threadIdx.x;
    if (i < NHN) { g_cnt[0][i] = 0; g_cnt[1][i] = 0; }
}

__global__ void k_hist2(const int* __restrict__ ei0, const int* __restrict__ ei1) {
    int rel = blockIdx.y;
    const int* ei = rel ? ei1 : ei0;
    int e = blockIdx.x * blockDim.x + threadIdx.x;
    if (e >= NE) return;
    atomicAdd(&g_cnt[rel][ei[NE + e]], 1);
}

__global__ void k_scan2() {
    int rel = blockIdx.x;
    __shared__ int part[1025];
    int T = blockDim.x, tid = threadIdx.x;
    int chunk = (NHN + T - 1) / T;
    int s0 = tid * chunk;
    int s1 = s0 + chunk; if (s1 > NHN) s1 = NHN;
    int s = 0;
    for (int i = s0; i < s1; i++) s += g_cnt[rel][i];
    part[tid] = s;
    __syncthreads();
    if (tid == 0) {
        int run = 0;
        for (int i = 0; i < T; i++) { int t = part[i]; part[i] = run; run += t; }
        part[T] = run;
    }
    __syncthreads();
    int run = part[tid];
    for (int i = s0; i < s1; i++) {
        g_rowptr[rel][i] = run;
        g_pos[rel][i] = run;
        run += g_cnt[rel][i];
    }
    if (tid == 0) g_rowptr[rel][NHN] = part[T];
}

__global__ void k_scatter2(const int* __restrict__ ei0, const float* __restrict__ ea0,
                           const int* __restrict__ ei1, const float* __restrict__ ea1) {
    int rel = blockIdx.y;
    const int* ei = rel ? ei1 : ei0;
    const float* ea = rel ? ea1 : ea0;
    int e = blockIdx.x * blockDim.x + threadIdx.x;
    if (e >= NE) return;
    int d = ei[NE + e];
    int p = atomicAdd(&g_pos[rel][d], 1);
    g_srcP[rel][p] = ei[e];
    g_eaP[rel][p] = ((const float2*)ea)[e];
}

// ============ mma.sync bf16 3-term split GEMM: C[50048,256] = A @ W ========
// BM=128, BN=128, BK=32, 256 thr (8 warps 2x4), warp tile 64x32.
// 2-stage cp.async double buffer; 2 CTAs/SM for barrier/latency hiding.
#define GSM_STAGE 40960
#define GSM_TOTAL 81920

__global__ void __launch_bounds__(256, 2) k_gemm_mma(int l) {
    extern __shared__ char smem[];
    int sel = blockIdx.z;
    const __nv_bfloat16* Agh = sel ? g_xoh : g_xhh;
    const __nv_bfloat16* Agl = sel ? g_xol : g_xhl;
    const __nv_bfloat16* Bgh = g_Bh + (size_t)(sel * NL + l) * DIM * DIM;
    const __nv_bfloat16* Bgl = g_Bl + (size_t)(sel * NL + l) * DIM * DIM;
    float* Cm = sel ? g_hs1 : g_hs0;

    int tid = threadIdx.x, lane = tid & 31, wid = tid >> 5;
    int warpM = wid & 1, warpN = wid >> 1;
    int rowBase = blockIdx.x * 128;
    int colBase = blockIdx.y * 128;
    uint32_t sb = smem_u32(smem);

    float acc[16][4];
#pragma unroll
    for (int i = 0; i < 16; i++)
#pragma unroll
        for (int j = 0; j < 4; j++) acc[i][j] = 0.f;

    int c0 = tid * 2;
    int rA0 = (c0) >> 2, kch0 = (c0) & 3;
    int rA1 = (c0 + 1) >> 2, kch1 = (c0 + 1) & 3;

    int rowA = (lane & 7) + 8 * ((lane >> 3) & 1);
    int chA = lane >> 4;
    int rowB = (lane & 7) + 8 * (lane >> 4);
    int chB = (lane >> 3) & 1;

#define LOAD_STAGE(kc, stg) do {                                              \
    uint32_t stb = sb + (stg) * GSM_STAGE;                                    \
    size_t ga0 = ((size_t)(rowBase + rA0)) * DIM + (kc) * 32 + kch0 * 8;      \
    size_t ga1 = ((size_t)(rowBase + rA1)) * DIM + (kc) * 32 + kch1 * 8;      \
    size_t gb0 = ((size_t)(colBase + rA0)) * DIM + (kc) * 32 + kch0 * 8;      \
    size_t gb1 = ((size_t)(colBase + rA1)) * DIM + (kc) * 32 + kch1 * 8;      \
    uint32_t d0 = stb + rA0 * 80 + kch0 * 16;                                 \
    uint32_t d1 = stb + rA1 * 80 + kch1 * 16;                                 \
    cp16(d0, Agh + ga0);          cp16(d1, Agh + ga1);                        \
    cp16(d0 + 10240, Agl + ga0);  cp16(d1 + 10240, Agl + ga1);                \
    cp16(d0 + 20480, Bgh + gb0);  cp16(d1 + 20480, Bgh + gb1);                \
    cp16(d0 + 30720, Bgl + gb0);  cp16(d1 + 30720, Bgl + gb1);                \
    asm volatile("cp.async.commit_group;" ::: "memory");                      \
} while (0)

    LOAD_STAGE(0, 0);

#pragma unroll 1
    for (int kc = 0; kc < 8; kc++) {
        if (kc < 7) {
            LOAD_STAGE(kc + 1, (kc + 1) & 1);
            asm volatile("cp.async.wait_group 1;" ::: "memory");
        } else {
            asm volatile("cp.async.wait_group 0;" ::: "memory");
        }
        __syncthreads();

        uint32_t stb = sb + (kc & 1) * GSM_STAGE;
#pragma unroll
        for (int k16 = 0; k16 < 2; k16++) {
            uint32_t kb = k16 * 32;
            uint32_t fah[4][4], fal[4][4];
#pragma unroll
            for (int i = 0; i < 4; i++) {
                uint32_t a = stb + (uint32_t)(warpM * 64 + i * 16 + rowA) * 80 + kb + chA * 16;
                ldm4(fah[i], a);
                ldm4(fal[i], a + 10240);
            }
            uint32_t fbh[4][2], fbl[4][2];
#pragma unroll
            for (int j = 0; j < 2; j++) {
                uint32_t a = stb + 20480 + (uint32_t)(warpN * 32 + j * 16 + rowB) * 80 + kb + chB * 16;
                uint32_t t[4];
                ldm4(t, a);
                fbh[2 * j][0] = t[0]; fbh[2 * j][1] = t[1];
                fbh[2 * j + 1][0] = t[2]; fbh[2 * j + 1][1] = t[3];
                ldm4(t, a + 10240);
                fbl[2 * j][0] = t[0]; fbl[2 * j][1] = t[1];
                fbl[2 * j + 1][0] = t[2]; fbl[2 * j + 1][1] = t[3];
            }
#pragma unroll
            for (int i = 0; i < 4; i++)
#pragma unroll
                for (int j = 0; j < 4; j++) {
                    mma16816(acc[i * 4 + j], fah[i], fbh[j]);
                    mma16816(acc[i * 4 + j], fah[i], fbl[j]);
                    mma16816(acc[i * 4 + j], fal[i], fbh[j]);
                }
        }
        __syncthreads();
    }

#pragma unroll
    for (int i = 0; i < 4; i++) {
        int r0 = rowBase + warpM * 64 + i * 16 + (lane >> 2);
#pragma unroll
        for (int j = 0; j < 4; j++) {
            int c = colBase + warpN * 32 + j * 8 + 2 * (lane & 3);
            float* cp = Cm + (size_t)r0 * DIM + c;
            if (r0 < NHN) *(float2*)cp = make_float2(acc[i * 4 + j][0], acc[i * 4 + j][1]);
            if (r0 + 8 < NHN)
                *(float2*)(cp + 8 * DIM) = make_float2(acc[i * 4 + j][2], acc[i * 4 + j][3]);
        }
    }
}

// initial a_s/a_d (layer 0) straight from input tensors; sel = blockIdx.y
__global__ void k_attn0(const float* __restrict__ xh, const float* __restrict__ xo) {
    int sel = blockIdx.y;
    int w = (blockIdx.x * blockDim.x + threadIdx.x) >> 5;
    if (w >= NHN) return;
    int lane = threadIdx.x & 31;
    const float* x = sel ? xo : xh;
    const float* u = sel ? &g_uv[2][0] : &g_uv[0][0];
    const float* v = sel ? &g_uv[1][0] : &g_uv[3][0];
    float* as_out = sel ? g_as[0][1] : g_as[0][0];
    float* ad_out = sel ? g_ad[0][0] : g_ad[0][1];
    const float4* xr = (const float4*)&x[(size_t)w * DIM];
    float4 x0 = xr[lane * 2], x1 = xr[lane * 2 + 1];
    const float4* ur = (const float4*)u;
    const float4* vr = (const float4*)v;
    float4 u0 = ur[lane * 2], u1 = ur[lane * 2 + 1];
    float4 v0 = vr[lane * 2], v1 = vr[lane * 2 + 1];
    float su = x0.x * u0.x + x0.y * u0.y + x0.z * u0.z + x0.w * u0.w +
               x1.x * u1.x + x1.y * u1.y + x1.z * u1.z + x1.w * u1.w;
    float sv = x0.x * v0.x + x0.y * v0.y + x0.z * v0.z + x0.w * v0.w +
               x1.x * v1.x + x1.y * v1.y + x1.z * v1.z + x1.w * v1.w;
#pragma unroll
    for (int off = 16; off > 0; off >>= 1) {
        su += __shfl_down_sync(0xffffffffu, su, off);
        sv += __shfl_down_sync(0xffffffffu, sv, off);
    }
    if (lane == 0) { as_out[w] = su; ad_out[w] = sv; }
}

// ===== fused per-layer edge kernel (single relation per launch; cp.async ring)
// Per-warp smem: 8 ring slots x 1KB (hs rows) + 1KB alpha cache = 9216 B.
// 8 warps/CTA => 73728 B dynamic smem; 3 CTAs/SM.
#define ESM_WARP 9216
#define ESM_TOTAL (8 * ESM_WARP)

__global__ void k_edge(int l, int rel, const float* __restrict__ bias_l,
                       const int* __restrict__ batch) {
    extern __shared__ char esm[];
    int w = (blockIdx.x * blockDim.x + threadIdx.x) >> 5;
    if (w >= NHN) return;
    int lane = threadIdx.x & 31;
    int warp = threadIdx.x >> 5;
    char* wsm = esm + warp * ESM_WARP;            // ring base (8 x 1KB)
    float* s_alpha = (float*)(wsm + 8192);        // 256 alphas
    int buf = l & 1;
    int lastLayer = (l == NL - 1);
    const float* hs = rel ? g_hs1 : g_hs0;
    __nv_bfloat16* xhh = rel ? g_xhh : g_xoh;     // dst-side feature hi
    __nv_bfloat16* xhl = rel ? g_xhl : g_xol;
    const float c0 = g_c[rel * NL * 2 + l * 2 + 0];
    const float c1 = g_c[rel * NL * 2 + l * 2 + 1];
    const float* __restrict__ asv = g_as[buf][rel];
    const float ad = g_ad[buf][rel][w];
    const int* __restrict__ srcP = g_srcP[rel];
    int s0 = g_rowptr[rel][w], s1 = g_rowptr[rel][w + 1];
    int deg = s1 - s0;
    int col = lane * 8;

    // pass 1: online softmax stats (per-lane, then warp merge); cache <=8 slots
    float m = -3.4e38f, den = 0.f;
    float llg[8] = {0.f, 0.f, 0.f, 0.f, 0.f, 0.f, 0.f, 0.f};
#pragma unroll
    for (int slot = 0; slot < 8; slot++) {
        int p = s0 + slot * 32 + lane;
        if (p < s1) {
            int s = srcP[p];
            float2 ea = g_eaP[rel][p];
            float lg = asv[s] + ad + ea.x * c0 + ea.y * c1;
            lg = lg > 0.f ? lg : 0.2f * lg;
            llg[slot] = lg;
            float mn = fmaxf(m, lg);
            den = den * __expf(m - mn) + __expf(lg - mn);
            m = mn;
        }
    }
    for (int p = s0 + 256 + lane; p < s1; p += 32) {  // overflow (deg>256), ~never
        int s = srcP[p];
        float2 ea = g_eaP[rel][p];
        float lg = asv[s] + ad + ea.x * c0 + ea.y * c1;
        lg = lg > 0.f ? lg : 0.2f * lg;
        float mn = fmaxf(m, lg);
        den = den * __expf(m - mn) + __expf(lg - mn);
        m = mn;
    }
#pragma unroll
    for (int off = 16; off > 0; off >>= 1) {
        float m2 = __shfl_xor_sync(0xffffffffu, m, off);
        float d2 = __shfl_xor_sync(0xffffffffu, den, off);
        float mn = fmaxf(m, m2);
        den = den * __expf(m - mn) + d2 * __expf(m2 - mn);
        m = mn;
    }
    float inv = deg > 0 ? 1.f / den : 0.f;

    // write alpha cache (first 256 edges) to smem
#pragma unroll
    for (int slot = 0; slot < 8; slot++) {
        int p = s0 + slot * 32 + lane;
        if (p < s1) s_alpha[slot * 32 + lane] = __expf(llg[slot] - m) * inv;
    }
    __syncwarp();

    // pass 2: cp.async ring pipeline; 8 slots, 7 groups in flight, distance 7.
    uint32_t ring = smem_u32(wsm);
    int pro = deg < 7 ? deg : 7;
    for (int i = 0; i < pro; i++) {
        int s = srcP[s0 + i];
        const char* sp = (const char*)hs + (size_t)s * 1024 + lane * 32;
        uint32_t dst = ring + (uint32_t)(i & 7) * 1024 + lane * 32;
        cp16(dst, sp);
        cp16(dst + 16, sp + 16);
        asm volatile("cp.async.commit_group;" ::: "memory");
    }
    for (int i = pro; i < 7; i++)
        asm volatile("cp.async.commit_group;" ::: "memory");

    float acc[8] = {0.f, 0.f, 0.f, 0.f, 0.f, 0.f, 0.f, 0.f};
#pragma unroll 1
    for (int i = 0; i < deg; i++) {
        asm volatile("cp.async.wait_group 6;" ::: "memory");
        const float4* hp = (const float4*)(wsm + (size_t)(i & 7) * 1024 + (size_t)lane * 32);
        float4 h0 = hp[0], h1 = hp[1];
        float al;
        if (i < 256) {
            al = s_alpha[i];
        } else {
            int p = s0 + i;
            int s = srcP[p];
            float2 ea = g_eaP[rel][p];
            float lg = asv[s] + ad + ea.x * c0 + ea.y * c1;
            lg = lg > 0.f ? lg : 0.2f * lg;
            al = __expf(lg - m) * inv;
        }
        acc[0] += al * h0.x; acc[1] += al * h0.y;
        acc[2] += al * h0.z; acc[3] += al * h0.w;
        acc[4] += al * h1.x; acc[5] += al * h1.y;
        acc[6] += al * h1.z; acc[7] += al * h1.w;
        int nj = i + 7;
        if (nj < deg) {
            int s = srcP[s0 + nj];
            const char* sp = (const char*)hs + (size_t)s * 1024 + lane * 32;
            uint32_t dst = ring + (uint32_t)(nj & 7) * 1024 + lane * 32;
            cp16(dst, sp);
            cp16(dst + 16, sp + 16);
        }
        asm volatile("cp.async.commit_group;" ::: "memory");
    }
    asm volatile("cp.async.wait_group 0;" ::: "memory");

    // epilogue: bias + relu + residual (residual from bf16 hi/lo pair)
    float4 b0 = *(const float4*)&bias_l[col];
    float4 b1 = *(const float4*)&bias_l[col + 4];
    float o[8];
    o[0] = fmaxf(acc[0] + b0.x, 0.f); o[1] = fmaxf(acc[1] + b0.y, 0.f);
    o[2] = fmaxf(acc[2] + b0.z, 0.f); o[3] = fmaxf(acc[3] + b0.w, 0.f);
    o[4] = fmaxf(acc[4] + b1.x, 0.f); o[5] = fmaxf(acc[5] + b1.y, 0.f);
    o[6] = fmaxf(acc[6] + b1.z, 0.f); o[7] = fmaxf(acc[7] + b1.w, 0.f);
    size_t xoff = (size_t)w * DIM + col;
    if (l > 0) {
        union { uint4 u; __nv_bfloat16 h[8]; } rh, rl;
        rh.u = *(const uint4*)&xhh[xoff];
        rl.u = *(const uint4*)&xhl[xoff];
#pragma unroll
        for (int j = 0; j < 8; j++)
            o[j] += __bfloat162float(rh.h[j]) + __bfloat162float(rl.h[j]);
    }

    if (!lastLayer) {
        union { uint4 u; __nv_bfloat16 h[8]; } ph, pl;
#pragma unroll
        for (int j = 0; j < 8; j++) {
            __nv_bfloat16 h = __float2bfloat16(o[j]);
            ph.h[j] = h;
            pl.h[j] = __float2bfloat16(o[j] - __bfloat162float(h));
        }
        *(uint4*)&xhh[xoff] = ph.u;
        *(uint4*)&xhl[xoff] = pl.u;
        // next layer's attention scalars from registers
        const float* u = rel ? &g_uv[0][(l + 1) * DIM] : &g_uv[2][(l + 1) * DIM];
        const float* v = rel ? &g_uv[3][(l + 1) * DIM] : &g_uv[1][(l + 1) * DIM];
        float su = 0.f, sv = 0.f;
#pragma unroll
        for (int j = 0; j < 8; j++) {
            su += o[j] * u[col + j];
            sv += o[j] * v[col + j];
        }
#pragma unroll
        for (int off = 16; off > 0; off >>= 1) {
            su += __shfl_down_sync(0xffffffffu, su, off);
            sv += __shfl_down_sync(0xffffffffu, sv, off);
        }
        if (lane == 0) {
            int nbuf = buf ^ 1;
            (rel ? g_as[nbuf][0] : g_as[nbuf][1])[w] = su;
            (rel ? g_ad[nbuf][1] : g_ad[nbuf][0])[w] = sv;
        }
    } else {
        // final layer: pool directly (mean over batch segments)
        float* pool = rel ? g_hpool : g_opool;
        int* cnt = rel ? g_cnth : g_cnto;
        int b = batch[w];
        float* pr = &pool[b * DIM + col];
        atomicAdd(pr + 0, o[0]); atomicAdd(pr + 1, o[1]);
        atomicAdd(pr + 2, o[2]); atomicAdd(pr + 3, o[3]);
        atomicAdd(pr + 4, o[4]); atomicAdd(pr + 5, o[5]);
        atomicAdd(pr + 6, o[6]); atomicAdd(pr + 7, o[7]);
        if (lane == 0) atomicAdd(&cnt[b], 1);
    }
}

__global__ void k_zero_pools() {
    int i = blockIdx.x * blockDim.x + threadIdx.x;
    if (i < NB * DIM) { g_hpool[i] = 0.f; g_opool[i] = 0.f; }
    if (i < NB * 32) g_epool[i] = 0.f;
    if (i < NB) { g_cnth[i] = 0; g_cnto[i] = 0; g_cnte[i] = 0; }
}

__global__ void k_epool(const int* __restrict__ ei, const float* __restrict__ ea,
                        const int* __restrict__ hbatch,
                        const float* __restrict__ Wm, const float* __restrict__ bm) {
    int e = (blockIdx.x * blockDim.x + threadIdx.x) >> 5;
    if (e >= NE) return;
    int lane = threadIdx.x & 31;
    int src = ei[e];
    int b = hbatch[src];
    float2 eav = ((const float2*)ea)[e];
    float val = eav.x * Wm[lane] + eav.y * Wm[32 + lane] + bm[lane];
    val = fmaxf(val, 0.f);
    atomicAdd(&g_epool[b * 32 + lane], val);
    if (lane == 0) atomicAdd(&g_cnte[b], 1);
}

__global__ void k_final(const float* __restrict__ Wp1, const float* __restrict__ bp1,
                        const float* __restrict__ Wp2, const float* __restrict__ bp2,
                        float* __restrict__ out) {
    __shared__ float emb[544];
    __shared__ float logits[240];
    __shared__ float mred[2], sred[2];
    int b = blockIdx.x, t = threadIdx.x;
    float ch = fmaxf((float)g_cnth[b], 1.f);
    float co = fmaxf((float)g_cnto[b], 1.f);
    float ce = fmaxf((float)g_cnte[b], 1.f);
    emb[t] = g_hpool[b * DIM + t] / ch;
    emb[256 + t] = g_opool[b * DIM + t] / co;
    if (t < 32) emb[512 + t] = g_epool[b * 32 + t] / ce;
    __syncthreads();
    if (t < 2 * NC) {
        int head = (t < NC) ? 0 : 1;
        int c = head ? (t - NC) : t;
        const float* W = head ? Wp2 : Wp1;
        const float* bb = head ? bp2 : bp1;
        float s = bb[c];
        for (int k = 0; k < 544; k++) s += emb[k] * W[k * NC + c];
        logits[t] = s;
    }
    __syncthreads();
    if (t < 2) {
        float m = -3.4e38f;
        for (int i = 0; i < NC; i++) m = fmaxf(m, logits[t * NC + i]);
        float sum = 0.f;
        for (int i = 0; i < NC; i++) sum += expf(logits[t * NC + i] - m);
        mred[t] = m; sred[t] = sum;
    }
    __syncthreads();
    if (t < 2 * NC) {
        int head = (t < NC) ? 0 : 1;
        out[(size_t)b * 2 * NC + t] = expf(logits[t] - mred[head]) / sred[head];
    }
}

// ---------------- launch ----------------
extern "C" void kernel_launch(void* const* d_in, const int* in_sizes, int n_in,
                              void* d_out, int out_size) {
    const float* x_human = (const float*)d_in[0];
    const float* x_object = (const float*)d_in[1];
    const int* ei_ho = (const int*)d_in[2];
    const int* ei_oh = (const int*)d_in[3];
    const float* ea_ho = (const float*)d_in[4];
    const float* ea_oh = (const float*)d_in[5];
    const int* hbatch = (const int*)d_in[6];
    const int* obatch = (const int*)d_in[7];
    const float* Wsrc_ho = (const float*)d_in[8];
    const float* Wdst_ho = (const float*)d_in[9];
    const float* asrc_ho = (const float*)d_in[10];
    const float* adst_ho = (const float*)d_in[11];
    const float* Wedge_ho = (const float*)d_in[12];
    const float* aedge_ho = (const float*)d_in[13];
    const float* bias_ho = (const float*)d_in[14];
    const float* Wsrc_oh = (const float*)d_in[15];
    const float* Wdst_oh = (const float*)d_in[16];
    const float* asrc_oh = (const float*)d_in[17];
    const float* adst_oh = (const float*)d_in[18];
    const float* Wedge_oh = (const float*)d_in[19];
    const float* aedge_oh = (const float*)d_in[20];
    const float* bias_oh = (const float*)d_in[21];
    const float* W_emlp = (const float*)d_in[22];
    const float* b_emlp = (const float*)d_in[23];
    const float* W_p1 = (const float*)d_in[24];
    const float* b_p1 = (const float*)d_in[25];
    const float* W_p2 = (const float*)d_in[26];
    const float* b_p2 = (const float*)d_in[27];
    float* out = (float*)d_out;

    cudaFuncSetAttribute(k_gemm_mma, cudaFuncAttributeMaxDynamicSharedMemorySize,
                         GSM_TOTAL);
    cudaFuncSetAttribute(k_edge, cudaFuncAttributeMaxDynamicSharedMemorySize,
                         ESM_TOTAL);

    const int T = 256;
    dim3 gemmGrid(NMP / 128, DIM / 128, 2);   // (391, 2, 2)
    int warpBlocks = (NHN * 32 + T - 1) / T;
    int neBlocks = (NE + T - 1) / T;

    k_copy_x<<<(NHN * DIM + T - 1) / T, T>>>(x_human, x_object);
    k_prepW<<<(2 * NL * DIM * DIM + T - 1) / T, T>>>(Wsrc_ho, Wsrc_oh);
    k_zero_csr<<<(NHN + T - 1) / T, T>>>();
    k_hist2<<<dim3(neBlocks, 2), T>>>(ei_ho, ei_oh);
    k_scan2<<<2, 1024>>>();
    k_gemm_mma<<<gemmGrid, 256, GSM_TOTAL>>>(0);
    k_scatter2<<<dim3(neBlocks, 2), T>>>(ei_ho, ea_ho, ei_oh, ea_oh);
    k_matrow4<<<dim3((NL * DIM * 32 + T - 1) / T, 4), T>>>(
        Wsrc_ho, asrc_ho, Wdst_ho, adst_ho, Wsrc_oh, asrc_oh, Wdst_oh, adst_oh);
    k_cdot2<<<2, 32>>>(Wedge_ho, aedge_ho, Wedge_oh, aedge_oh);
    k_attn0<<<dim3(warpBlocks, 2), T>>>(x_human, x_object);
    k_zero_pools<<<(NB * DIM + T - 1) / T, T>>>();
    k_epool<<<(NE * 32 + T - 1) / T, T>>>(ei_ho, ea_ho, hbatch, W_emlp, b_emlp);

    for (int l = 0; l < NL; l++) {
        if (l > 0) k_gemm_mma<<<gemmGrid, 256, GSM_TOTAL>>>(l);
        // sequential relations: each launch's gather set (one hs side) fits L2
        k_edge<<<warpBlocks, T, ESM_TOTAL>>>(l, 0, bias_ho + l * DIM, obatch);
        k_edge<<<warpBlocks, T, ESM_TOTAL>>>(l, 1, bias_oh + l * DIM, hbatch);
    }

    k_final<<<NB, T>>>(W_p1, b_p1, W_p2, b_p2, out);
}

// round 16
// speedup vs baseline: 1.1558x; 1.1558x over previous
#include <cuda_runtime.h>
#include <cuda_bf16.h>
#include <cstdint>

#define NHN 50000
#define NON 50000
#define NMP 50048   // padded rows (391 * 128)
#define NE  500000
#define DIM 256
#define NL  8
#define NB  512
#define NC  117

// ---------------- device scratch (no allocations allowed) ----------------
__device__ float g_hs0[NHN * DIM];
__device__ float g_hs1[NON * DIM];
__device__ float g_as[2][2][NHN];   // [layer parity][rel]
__device__ float g_ad[2][2][NHN];   // [layer parity][rel]
__device__ float g_uv[4][NL * DIM];
__device__ float g_c[2 * NL * 2];

// bf16 hi/lo split node features (padded to NMP rows, zero-init pad).
// These ARE the node state; fp32 value = hi + lo (error ~2^-18).
__device__ __nv_bfloat16 g_xhh[NMP * DIM];
__device__ __nv_bfloat16 g_xhl[NMP * DIM];
__device__ __nv_bfloat16 g_xoh[NMP * DIM];
__device__ __nv_bfloat16 g_xol[NMP * DIM];

// W^T split: [rel*NL+l][n][k] bf16
__device__ __nv_bfloat16 g_Bh[2 * NL * DIM * DIM];
__device__ __nv_bfloat16 g_Bl[2 * NL * DIM * DIM];

__device__ int    g_cnt[2][NHN];
__device__ int    g_rowptr[2][NHN + 1];
__device__ int    g_pos[2][NHN];
__device__ int    g_srcP[2][NE];
__device__ float2 g_eaP[2][NE];

__device__ float g_hpool[NB * DIM];
__device__ float g_opool[NB * DIM];
__device__ float g_epool[NB * 32];
__device__ int   g_cnth[NB];
__device__ int   g_cnto[NB];
__device__ int   g_cnte[NB];

// ================= portable PTX helpers (sm_80+ features only) =============
__device__ __forceinline__ uint32_t smem_u32(const void* p) {
    uint32_t a;
    asm("{ .reg .u64 t; cvta.to.shared.u64 t, %1; cvt.u32.u64 %0, t; }"
        : "=r"(a) : "l"(p));
    return a;
}

__device__ __forceinline__ void cp16(uint32_t s, const void* g) {
    asm volatile("cp.async.cg.shared.global [%0], [%1], 16;" :: "r"(s), "l"(g) : "memory");
}

__device__ __forceinline__ void ldm4(uint32_t* r, uint32_t addr) {
    asm volatile("ldmatrix.sync.aligned.m8n8.x4.shared.b16 {%0,%1,%2,%3}, [%4];"
                 : "=r"(r[0]), "=r"(r[1]), "=r"(r[2]), "=r"(r[3]) : "r"(addr));
}

__device__ __forceinline__ void mma16816(float* c, const uint32_t* a, const uint32_t* b) {
    asm volatile(
        "mma.sync.aligned.m16n8k16.row.col.f32.bf16.bf16.f32 "
        "{%0,%1,%2,%3}, {%4,%5,%6,%7}, {%8,%9}, {%0,%1,%2,%3};"
        : "+f"(c[0]), "+f"(c[1]), "+f"(c[2]), "+f"(c[3])
        : "r"(a[0]), "r"(a[1]), "r"(a[2]), "r"(a[3]), "r"(b[0]), "r"(b[1]));
}

// ---------------- small kernels ----------------

__global__ void k_copy_x(const float* __restrict__ xh, const float* __restrict__ xo) {
    int i = blockIdx.x * blockDim.x + threadIdx.x;
    if (i < NHN * DIM) {
        float v = xh[i];
        __nv_bfloat16 h = __float2bfloat16(v);
        g_xhh[i] = h;
        g_xhl[i] = __float2bfloat16(v - __bfloat162float(h));
    }
    if (i < NON * DIM) {
        float v = xo[i];
        __nv_bfloat16 h = __float2bfloat16(v);
        g_xoh[i] = h;
        g_xol[i] = __float2bfloat16(v - __bfloat162float(h));
    }
}

// all four uv vectors in one launch; which = blockIdx.y
__global__ void k_matrow4(const float* __restrict__ W0, const float* __restrict__ a0,
                          const float* __restrict__ W1, const float* __restrict__ a1,
                          const float* __restrict__ W2, const float* __restrict__ a2,
                          const float* __restrict__ W3, const float* __restrict__ a3) {
    int which = blockIdx.y;
    const float* W = which == 0 ? W0 : which == 1 ? W1 : which == 2 ? W2 : W3;
    const float* a = which == 0 ? a0 : which == 1 ? a1 : which == 2 ? a2 : a3;
    int g = (blockIdx.x * blockDim.x + threadIdx.x) >> 5;
    if (g >= NL * DIM) return;
    int lane = threadIdx.x & 31;
    int l = g >> 8, i = g & 255;
    const float* wr = W + (size_t)l * DIM * DIM + (size_t)i * DIM;
    const float* ar = a + l * DIM;
    float s = 0.f;
    for (int j = lane; j < DIM; j += 32) s += wr[j] * ar[j];
#pragma unroll
    for (int off = 16; off > 0; off >>= 1) s += __shfl_down_sync(0xffffffffu, s, off);
    if (lane == 0) g_uv[which][g] = s;
}

// both relations' edge coefficients; rel = blockIdx.x
__global__ void k_cdot2(const float* __restrict__ We0, const float* __restrict__ ae0,
                        const float* __restrict__ We1, const float* __restrict__ ae1) {
    int rel = blockIdx.x;
    const float* We = rel ? We1 : We0;
    const float* ae = rel ? ae1 : ae0;
    int idx = threadIdx.x;
    if (idx >= NL * 2) return;
    int l = idx >> 1, k = idx & 1;
    const float* wr = We + (size_t)l * 2 * DIM + (size_t)k * DIM;
    const float* ar = ae + l * DIM;
    float s = 0.f;
    for (int j = 0; j < DIM; j++) s += wr[j] * ar[j];
    g_c[rel * NL * 2 + l * 2 + k] = s;
}

// W[l][k][n] -> Bh/Bl[(rel*NL+l)][n][k] (transpose + hi/lo split)
__global__ void k_prepW(const float* __restrict__ Wh, const float* __restrict__ Wo) {
    int idx = blockIdx.x * blockDim.x + threadIdx.x;
    if (idx >= 2 * NL * DIM * DIM) return;
    int rel = idx / (NL * DIM * DIM);
    int r = idx % (NL * DIM * DIM);
    int l = r / (DIM * DIM);
    int kk = (r / DIM) % DIM;
    int n = r % DIM;
    const float* W = rel ? Wo : Wh;
    float w = W[(size_t)l * DIM * DIM + (size_t)kk * DIM + n];
    __nv_bfloat16 hi = __float2bfloat16(w);
    __nv_bfloat16 lo = __float2bfloat16(w - __bfloat162float(hi));
    size_t dst = ((size_t)(rel * NL + l) * DIM + n) * DIM + kk;
    g_Bh[dst] = hi;
    g_Bl[dst] = lo;
}

__global__ void k_zero_csr() {
    int i = blockIdx.x * blockDim.x + threadIdx.x;
    if (i < NHN) { g_cnt[0][i] = 0; g_cnt[1][i] = 0; }
}

__global__ void k_hist2(const int* __restrict__ ei0, const int* __restrict__ ei1) {
    int rel = blockIdx.y;
    const int* ei = rel ? ei1 : ei0;
    int e = blockIdx.x * blockDim.x + threadIdx.x;
    if (e >= NE) return;
    atomicAdd(&g_cnt[rel][ei[NE + e]], 1);
}

__global__ void k_scan2() {
    int rel = blockIdx.x;
    __shared__ int part[1025];
    int T = blockDim.x, tid = threadIdx.x;
    int chunk = (NHN + T - 1) / T;
    int s0 = tid * chunk;
    int s1 = s0 + chunk; if (s1 > NHN) s1 = NHN;
    int s = 0;
    for (int i = s0; i < s1; i++) s += g_cnt[rel][i];
    part[tid] = s;
    __syncthreads();
    if (tid == 0) {
        int run = 0;
        for (int i = 0; i < T; i++) { int t = part[i]; part[i] = run; run += t; }
        part[T] = run;
    }
    __syncthreads();
    int run = part[tid];
    for (int i = s0; i < s1; i++) {
        g_rowptr[rel][i] = run;
        g_pos[rel][i] = run;
        run += g_cnt[rel][i];
    }
    if (tid == 0) g_rowptr[rel][NHN] = part[T];
}

__global__ void k_scatter2(const int* __restrict__ ei0, const float* __restrict__ ea0,
                           const int* __restrict__ ei1, const float* __restrict__ ea1) {
    int rel = blockIdx.y;
    const int* ei = rel ? ei1 : ei0;
    const float* ea = rel ? ea1 : ea0;
    int e = blockIdx.x * blockDim.x + threadIdx.x;
    if (e >= NE) return;
    int d = ei[NE + e];
    int p = atomicAdd(&g_pos[rel][d], 1);
    g_srcP[rel][p] = ei[e];
    g_eaP[rel][p] = ((const float2*)ea)[e];
}

// ============ mma.sync bf16 3-term split GEMM: C[50048,256] = A @ W ========
// BM=128, BN=128, BK=32, 256 thr (8 warps 2x4), warp tile 64x32.
// 2-stage cp.async double buffer; 2 CTAs/SM for barrier/latency hiding.
#define GSM_STAGE 40960
#define GSM_TOTAL 81920

__global__ void __launch_bounds__(256, 2) k_gemm_mma(int l) {
    extern __shared__ char smem[];
    int sel = blockIdx.z;
    const __nv_bfloat16* Agh = sel ? g_xoh : g_xhh;
    const __nv_bfloat16* Agl = sel ? g_xol : g_xhl;
    const __nv_bfloat16* Bgh = g_Bh + (size_t)(sel * NL + l) * DIM * DIM;
    const __nv_bfloat16* Bgl = g_Bl + (size_t)(sel * NL + l) * DIM * DIM;
    float* Cm = sel ? g_hs1 : g_hs0;

    int tid = threadIdx.x, lane = tid & 31, wid = tid >> 5;
    int warpM = wid & 1, warpN = wid >> 1;
    int rowBase = blockIdx.x * 128;
    int colBase = blockIdx.y * 128;
    uint32_t sb = smem_u32(smem);

    float acc[16][4];
#pragma unroll
    for (int i = 0; i < 16; i++)
#pragma unroll
        for (int j = 0; j < 4; j++) acc[i][j] = 0.f;

    int c0 = tid * 2;
    int rA0 = (c0) >> 2, kch0 = (c0) & 3;
    int rA1 = (c0 + 1) >> 2, kch1 = (c0 + 1) & 3;

    int rowA = (lane & 7) + 8 * ((lane >> 3) & 1);
    int chA = lane >> 4;
    int rowB = (lane & 7) + 8 * (lane >> 4);
    int chB = (lane >> 3) & 1;

#define LOAD_STAGE(kc, stg) do {                                              \
    uint32_t stb = sb + (stg) * GSM_STAGE;                                    \
    size_t ga0 = ((size_t)(rowBase + rA0)) * DIM + (kc) * 32 + kch0 * 8;      \
    size_t ga1 = ((size_t)(rowBase + rA1)) * DIM + (kc) * 32 + kch1 * 8;      \
    size_t gb0 = ((size_t)(colBase + rA0)) * DIM + (kc) * 32 + kch0 * 8;      \
    size_t gb1 = ((size_t)(colBase + rA1)) * DIM + (kc) * 32 + kch1 * 8;      \
    uint32_t d0 = stb + rA0 * 80 + kch0 * 16;                                 \
    uint32_t d1 = stb + rA1 * 80 + kch1 * 16;                                 \
    cp16(d0, Agh + ga0);          cp16(d1, Agh + ga1);                        \
    cp16(d0 + 10240, Agl + ga0);  cp16(d1 + 10240, Agl + ga1);                \
    cp16(d0 + 20480, Bgh + gb0);  cp16(d1 + 20480, Bgh + gb1);                \
    cp16(d0 + 30720, Bgl + gb0);  cp16(d1 + 30720, Bgl + gb1);                \
    asm volatile("cp.async.commit_group;" ::: "memory");                      \
} while (0)

    LOAD_STAGE(0, 0);

#pragma unroll 1
    for (int kc = 0; kc < 8; kc++) {
        if (kc < 7) {
            LOAD_STAGE(kc + 1, (kc + 1) & 1);
            asm volatile("cp.async.wait_group 1;" ::: "memory");
        } else {
            asm volatile("cp.async.wait_group 0;" ::: "memory");
        }
        __syncthreads();

        uint32_t stb = sb + (kc & 1) * GSM_STAGE;
#pragma unroll
        for (int k16 = 0; k16 < 2; k16++) {
            uint32_t kb = k16 * 32;
            uint32_t fah[4][4], fal[4][4];
#pragma unroll
            for (int i = 0; i < 4; i++) {
                uint32_t a = stb + (uint32_t)(warpM * 64 + i * 16 + rowA) * 80 + kb + chA * 16;
                ldm4(fah[i], a);
                ldm4(fal[i], a + 10240);
            }
            uint32_t fbh[4][2], fbl[4][2];
#pragma unroll
            for (int j = 0; j < 2; j++) {
                uint32_t a = stb + 20480 + (uint32_t)(warpN * 32 + j * 16 + rowB) * 80 + kb + chB * 16;
                uint32_t t[4];
                ldm4(t, a);
                fbh[2 * j][0] = t[0]; fbh[2 * j][1] = t[1];
                fbh[2 * j + 1][0] = t[2]; fbh[2 * j + 1][1] = t[3];
                ldm4(t, a + 10240);
                fbl[2 * j][0] = t[0]; fbl[2 * j][1] = t[1];
                fbl[2 * j + 1][0] = t[2]; fbl[2 * j + 1][1] = t[3];
            }
#pragma unroll
            for (int i = 0; i < 4; i++)
#pragma unroll
                for (int j = 0; j < 4; j++) {
                    mma16816(acc[i * 4 + j], fah[i], fbh[j]);
                    mma16816(acc[i * 4 + j], fah[i], fbl[j]);
                    mma16816(acc[i * 4 + j], fal[i], fbh[j]);
                }
        }
        __syncthreads();
    }

#pragma unroll
    for (int i = 0; i < 4; i++) {
        int r0 = rowBase + warpM * 64 + i * 16 + (lane >> 2);
#pragma unroll
        for (int j = 0; j < 4; j++) {
            int c = colBase + warpN * 32 + j * 8 + 2 * (lane & 3);
            float* cp = Cm + (size_t)r0 * DIM + c;
            if (r0 < NHN) *(float2*)cp = make_float2(acc[i * 4 + j][0], acc[i * 4 + j][1]);
            if (r0 + 8 < NHN)
                *(float2*)(cp + 8 * DIM) = make_float2(acc[i * 4 + j][2], acc[i * 4 + j][3]);
        }
    }
}

// initial a_s/a_d (layer 0) straight from input tensors; sel = blockIdx.y
__global__ void k_attn0(const float* __restrict__ xh, const float* __restrict__ xo) {
    int sel = blockIdx.y;
    int w = (blockIdx.x * blockDim.x + threadIdx.x) >> 5;
    if (w >= NHN) return;
    int lane = threadIdx.x & 31;
    const float* x = sel ? xo : xh;
    const float* u = sel ? &g_uv[2][0] : &g_uv[0][0];
    const float* v = sel ? &g_uv[1][0] : &g_uv[3][0];
    float* as_out = sel ? g_as[0][1] : g_as[0][0];
    float* ad_out = sel ? g_ad[0][0] : g_ad[0][1];
    const float4* xr = (const float4*)&x[(size_t)w * DIM];
    float4 x0 = xr[lane * 2], x1 = xr[lane * 2 + 1];
    const float4* ur = (const float4*)u;
    const float4* vr = (const float4*)v;
    float4 u0 = ur[lane * 2], u1 = ur[lane * 2 + 1];
    float4 v0 = vr[lane * 2], v1 = vr[lane * 2 + 1];
    float su = x0.x * u0.x + x0.y * u0.y + x0.z * u0.z + x0.w * u0.w +
               x1.x * u1.x + x1.y * u1.y + x1.z * u1.z + x1.w * u1.w;
    float sv = x0.x * v0.x + x0.y * v0.y + x0.z * v0.z + x0.w * v0.w +
               x1.x * v1.x + x1.y * v1.y + x1.z * v1.z + x1.w * v1.w;
#pragma unroll
    for (int off = 16; off > 0; off >>= 1) {
        su += __shfl_down_sync(0xffffffffu, su, off);
        sv += __shfl_down_sync(0xffffffffu, sv, off);
    }
    if (lane == 0) { as_out[w] = su; ad_out[w] = sv; }
}

// ===== fused per-layer edge kernel (single relation per launch for L2 locality)
// Alpha cache in static smem kills dynamic-index shuffles; 4 rows in flight.
__global__ void k_edge(int l, int rel, const float* __restrict__ bias_l,
                       const int* __restrict__ batch) {
    __shared__ float s_alpha[8][256];
    int w = (blockIdx.x * blockDim.x + threadIdx.x) >> 5;
    if (w >= NHN) return;
    int lane = threadIdx.x & 31;
    int warp = threadIdx.x >> 5;
    float* salpha = s_alpha[warp];
    int buf = l & 1;
    int lastLayer = (l == NL - 1);
    const float* hs = rel ? g_hs1 : g_hs0;
    __nv_bfloat16* xhh = rel ? g_xhh : g_xoh;   // dst-side feature hi
    __nv_bfloat16* xhl = rel ? g_xhl : g_xol;
    const float c0 = g_c[rel * NL * 2 + l * 2 + 0];
    const float c1 = g_c[rel * NL * 2 + l * 2 + 1];
    const float* __restrict__ asv = g_as[buf][rel];
    const float ad = g_ad[buf][rel][w];
    const int* __restrict__ srcP = g_srcP[rel];
    int s0 = g_rowptr[rel][w], s1 = g_rowptr[rel][w + 1];
    int deg = s1 - s0;
    int col = lane * 8;

    // pass 1: online softmax stats (per-lane, then warp merge); cache <=8 slots
    float m = -3.4e38f, den = 0.f;
    float llg[8] = {0.f, 0.f, 0.f, 0.f, 0.f, 0.f, 0.f, 0.f};
#pragma unroll
    for (int slot = 0; slot < 8; slot++) {
        int p = s0 + slot * 32 + lane;
        if (p < s1) {
            int s = srcP[p];
            float2 ea = g_eaP[rel][p];
            float lg = asv[s] + ad + ea.x * c0 + ea.y * c1;
            lg = lg > 0.f ? lg : 0.2f * lg;
            llg[slot] = lg;
            float mn = fmaxf(m, lg);
            den = den * __expf(m - mn) + __expf(lg - mn);
            m = mn;
        }
    }
    for (int p = s0 + 256 + lane; p < s1; p += 32) {  // overflow (deg>256), ~never
        int s = srcP[p];
        float2 ea = g_eaP[rel][p];
        float lg = asv[s] + ad + ea.x * c0 + ea.y * c1;
        lg = lg > 0.f ? lg : 0.2f * lg;
        float mn = fmaxf(m, lg);
        den = den * __expf(m - mn) + __expf(lg - mn);
        m = mn;
    }
#pragma unroll
    for (int off = 16; off > 0; off >>= 1) {
        float m2 = __shfl_xor_sync(0xffffffffu, m, off);
        float d2 = __shfl_xor_sync(0xffffffffu, den, off);
        float mn = fmaxf(m, m2);
        den = den * __expf(m - mn) + d2 * __expf(m2 - mn);
        m = mn;
    }
    float inv = deg > 0 ? 1.f / den : 0.f;

    // alpha cache: first 256 edges (covers essentially all rows)
#pragma unroll
    for (int slot = 0; slot < 8; slot++) {
        int p = s0 + slot * 32 + lane;
        if (p < s1) salpha[slot * 32 + lane] = __expf(llg[slot] - m) * inv;
    }
    __syncwarp();

    // pass 2: weighted aggregation, 4 rows in flight per lane (no shuffles)
    float acc[8] = {0.f, 0.f, 0.f, 0.f, 0.f, 0.f, 0.f, 0.f};
    int nCached = deg < 256 ? deg : 256;
    int i = 0;
    for (; i + 3 < nCached; i += 4) {
        int sA = srcP[s0 + i];
        int sB = srcP[s0 + i + 1];
        int sC = srcP[s0 + i + 2];
        int sD = srcP[s0 + i + 3];
        float alA = salpha[i];
        float alB = salpha[i + 1];
        float alC = salpha[i + 2];
        float alD = salpha[i + 3];
        const float4* hpA = (const float4*)&hs[(size_t)sA * DIM + col];
        const float4* hpB = (const float4*)&hs[(size_t)sB * DIM + col];
        const float4* hpC = (const float4*)&hs[(size_t)sC * DIM + col];
        const float4* hpD = (const float4*)&hs[(size_t)sD * DIM + col];
        float4 a0 = hpA[0], a1 = hpA[1];
        float4 b0 = hpB[0], b1 = hpB[1];
        float4 cc0 = hpC[0], cc1 = hpC[1];
        float4 d0 = hpD[0], d1 = hpD[1];
        acc[0] += alA * a0.x + alB * b0.x + alC * cc0.x + alD * d0.x;
        acc[1] += alA * a0.y + alB * b0.y + alC * cc0.y + alD * d0.y;
        acc[2] += alA * a0.z + alB * b0.z + alC * cc0.z + alD * d0.z;
        acc[3] += alA * a0.w + alB * b0.w + alC * cc0.w + alD * d0.w;
        acc[4] += alA * a1.x + alB * b1.x + alC * cc1.x + alD * d1.x;
        acc[5] += alA * a1.y + alB * b1.y + alC * cc1.y + alD * d1.y;
        acc[6] += alA * a1.z + alB * b1.z + alC * cc1.z + alD * d1.z;
        acc[7] += alA * a1.w + alB * b1.w + alC * cc1.w + alD * d1.w;
    }
    for (; i < nCached; i++) {
        int s = srcP[s0 + i];
        float al = salpha[i];
        const float4* hp = (const float4*)&hs[(size_t)s * DIM + col];
        float4 h0 = hp[0], h1 = hp[1];
        acc[0] += al * h0.x; acc[1] += al * h0.y;
        acc[2] += al * h0.z; acc[3] += al * h0.w;
        acc[4] += al * h1.x; acc[5] += al * h1.y;
        acc[6] += al * h1.z; acc[7] += al * h1.w;
    }
    for (int p = s0 + 256; p < s1; p++) {  // overflow path, ~never
        int s = srcP[p];
        float2 ea = g_eaP[rel][p];
        float lg = asv[s] + ad + ea.x * c0 + ea.y * c1;
        lg = lg > 0.f ? lg : 0.2f * lg;
        float al = __expf(lg - m) * inv;
        const float4* hp = (const float4*)&hs[(size_t)s * DIM + col];
        float4 h0 = hp[0], h1 = hp[1];
        acc[0] += al * h0.x; acc[1] += al * h0.y;
        acc[2] += al * h0.z; acc[3] += al * h0.w;
        acc[4] += al * h1.x; acc[5] += al * h1.y;
        acc[6] += al * h1.z; acc[7] += al * h1.w;
    }

    // epilogue: bias + relu + residual (residual from bf16 hi/lo pair)
    float4 b0 = *(const float4*)&bias_l[col];
    float4 b1 = *(const float4*)&bias_l[col + 4];
    float o[8];
    o[0] = fmaxf(acc[0] + b0.x, 0.f); o[1] = fmaxf(acc[1] + b0.y, 0.f);
    o[2] = fmaxf(acc[2] + b0.z, 0.f); o[3] = fmaxf(acc[3] + b0.w, 0.f);
    o[4] = fmaxf(acc[4] + b1.x, 0.f); o[5] = fmaxf(acc[5] + b1.y, 0.f);
    o[6] = fmaxf(acc[6] + b1.z, 0.f); o[7] = fmaxf(acc[7] + b1.w, 0.f);
    size_t xoff = (size_t)w * DIM + col;
    if (l > 0) {
        union { uint4 u; __nv_bfloat16 h[8]; } rh, rl;
        rh.u = *(const uint4*)&xhh[xoff];
        rl.u = *(const uint4*)&xhl[xoff];
#pragma unroll
        for (int j = 0; j < 8; j++)
            o[j] += __bfloat162float(rh.h[j]) + __bfloat162float(rl.h[j]);
    }

    if (!lastLayer) {
        union { uint4 u; __nv_bfloat16 h[8]; } ph, pl;
#pragma unroll
        for (int j = 0; j < 8; j++) {
            __nv_bfloat16 h = __float2bfloat16(o[j]);
            ph.h[j] = h;
            pl.h[j] = __float2bfloat16(o[j] - __bfloat162float(h));
        }
        *(uint4*)&xhh[xoff] = ph.u;
        *(uint4*)&xhl[xoff] = pl.u;
        // next layer's attention scalars from registers
        const float* u = rel ? &g_uv[0][(l + 1) * DIM] : &g_uv[2][(l + 1) * DIM];
        const float* v = rel ? &g_uv[3][(l + 1) * DIM] : &g_uv[1][(l + 1) * DIM];
        float su = 0.f, sv = 0.f;
#pragma unroll
        for (int j = 0; j < 8; j++) {
            su += o[j] * u[col + j];
            sv += o[j] * v[col + j];
        }
#pragma unroll
        for (int off = 16; off > 0; off >>= 1) {
            su += __shfl_down_sync(0xffffffffu, su, off);
            sv += __shfl_down_sync(0xffffffffu, sv, off);
        }
        if (lane == 0) {
            int nbuf = buf ^ 1;
            (rel ? g_as[nbuf][0] : g_as[nbuf][1])[w] = su;
            (rel ? g_ad[nbuf][1] : g_ad[nbuf][0])[w] = sv;
        }
    } else {
        // final layer: pool directly (mean over batch segments)
        float* pool = rel ? g_hpool : g_opool;
        int* cnt = rel ? g_cnth : g_cnto;
        int b = batch[w];
        float* pr = &pool[b * DIM + col];
        atomicAdd(pr + 0, o[0]); atomicAdd(pr + 1, o[1]);
        atomicAdd(pr + 2, o[2]); atomicAdd(pr + 3, o[3]);
        atomicAdd(pr + 4, o[4]); atomicAdd(pr + 5, o[5]);
        atomicAdd(pr + 6, o[6]); atomicAdd(pr + 7, o[7]);
        if (lane == 0) atomicAdd(&cnt[b], 1);
    }
}

__global__ void k_zero_pools() {
    int i = blockIdx.x * blockDim.x + threadIdx.x;
    if (i < NB * DIM) { g_hpool[i] = 0.f; g_opool[i] = 0.f; }
    if (i < NB * 32) g_epool[i] = 0.f;
    if (i < NB) { g_cnth[i] = 0; g_cnto[i] = 0; g_cnte[i] = 0; }
}

__global__ void k_epool(const int* __restrict__ ei, const float* __restrict__ ea,
                        const int* __restrict__ hbatch,
                        const float* __restrict__ Wm, const float* __restrict__ bm) {
    int e = (blockIdx.x * blockDim.x + threadIdx.x) >> 5;
    if (e >= NE) return;
    int lane = threadIdx.x & 31;
    int src = ei[e];
    int b = hbatch[src];
    float2 eav = ((const float2*)ea)[e];
    float val = eav.x * Wm[lane] + eav.y * Wm[32 + lane] + bm[lane];
    val = fmaxf(val, 0.f);
    atomicAdd(&g_epool[b * 32 + lane], val);
    if (lane == 0) atomicAdd(&g_cnte[b], 1);
}

__global__ void k_final(const float* __restrict__ Wp1, const float* __restrict__ bp1,
                        const float* __restrict__ Wp2, const float* __restrict__ bp2,
                        float* __restrict__ out) {
    __shared__ float emb[544];
    __shared__ float logits[240];
    __shared__ float mred[2], sred[2];
    int b = blockIdx.x, t = threadIdx.x;
    float ch = fmaxf((float)g_cnth[b], 1.f);
    float co = fmaxf((float)g_cnto[b], 1.f);
    float ce = fmaxf((float)g_cnte[b], 1.f);
    emb[t] = g_hpool[b * DIM + t] / ch;
    emb[256 + t] = g_opool[b * DIM + t] / co;
    if (t < 32) emb[512 + t] = g_epool[b * 32 + t] / ce;
    __syncthreads();
    if (t < 2 * NC) {
        int head = (t < NC) ? 0 : 1;
        int c = head ? (t - NC) : t;
        const float* W = head ? Wp2 : Wp1;
        const float* bb = head ? bp2 : bp1;
        float s = bb[c];
        for (int k = 0; k < 544; k++) s += emb[k] * W[k * NC + c];
        logits[t] = s;
    }
    __syncthreads();
    if (t < 2) {
        float m = -3.4e38f;
        for (int i = 0; i < NC; i++) m = fmaxf(m, logits[t * NC + i]);
        float sum = 0.f;
        for (int i = 0; i < NC; i++) sum += expf(logits[t * NC + i] - m);
        mred[t] = m; sred[t] = sum;
    }
    __syncthreads();
    if (t < 2 * NC) {
        int head = (t < NC) ? 0 : 1;
        out[(size_t)b * 2 * NC + t] = expf(logits[t] - mred[head]) / sred[head];
    }
}

// ---------------- launch ----------------
extern "C" void kernel_launch(void* const* d_in, const int* in_sizes, int n_in,
                              void* d_out, int out_size) {
    const float* x_human = (const float*)d_in[0];
    const float* x_object = (const float*)d_in[1];
    const int* ei_ho = (const int*)d_in[2];
    const int* ei_oh = (const int*)d_in[3];
    const float* ea_ho = (const float*)d_in[4];
    const float* ea_oh = (const float*)d_in[5];
    const int* hbatch = (const int*)d_in[6];
    const int* obatch = (const int*)d_in[7];
    const float* Wsrc_ho = (const float*)d_in[8];
    const float* Wdst_ho = (const float*)d_in[9];
    const float* asrc_ho = (const float*)d_in[10];
    const float* adst_ho = (const float*)d_in[11];
    const float* Wedge_ho = (const float*)d_in[12];
    const float* aedge_ho = (const float*)d_in[13];
    const float* bias_ho = (const float*)d_in[14];
    const float* Wsrc_oh = (const float*)d_in[15];
    const float* Wdst_oh = (const float*)d_in[16];
    const float* asrc_oh = (const float*)d_in[17];
    const float* adst_oh = (const float*)d_in[18];
    const float* Wedge_oh = (const float*)d_in[19];
    const float* aedge_oh = (const float*)d_in[20];
    const float* bias_oh = (const float*)d_in[21];
    const float* W_emlp = (const float*)d_in[22];
    const float* b_emlp = (const float*)d_in[23];
    const float* W_p1 = (const float*)d_in[24];
    const float* b_p1 = (const float*)d_in[25];
    const float* W_p2 = (const float*)d_in[26];
    const float* b_p2 = (const float*)d_in[27];
    float* out = (float*)d_out;

    cudaFuncSetAttribute(k_gemm_mma, cudaFuncAttributeMaxDynamicSharedMemorySize,
                         GSM_TOTAL);

    const int T = 256;
    dim3 gemmGrid(NMP / 128, DIM / 128, 2);   // (391, 2, 2)
    int warpBlocks = (NHN * 32 + T - 1) / T;
    int neBlocks = (NE + T - 1) / T;

    k_copy_x<<<(NHN * DIM + T - 1) / T, T>>>(x_human, x_object);
    k_prepW<<<(2 * NL * DIM * DIM + T - 1) / T, T>>>(Wsrc_ho, Wsrc_oh);
    k_zero_csr<<<(NHN + T - 1) / T, T>>>();
    k_hist2<<<dim3(neBlocks, 2), T>>>(ei_ho, ei_oh);
    k_scan2<<<2, 1024>>>();
    k_gemm_mma<<<gemmGrid, 256, GSM_TOTAL>>>(0);
    k_scatter2<<<dim3(neBlocks, 2), T>>>(ei_ho, ea_ho, ei_oh, ea_oh);
    k_matrow4<<<dim3((NL * DIM * 32 + T - 1) / T, 4), T>>>(
        Wsrc_ho, asrc_ho, Wdst_ho, adst_ho, Wsrc_oh, asrc_oh, Wdst_oh, adst_oh);
    k_cdot2<<<2, 32>>>(Wedge_ho, aedge_ho, Wedge_oh, aedge_oh);
    k_attn0<<<dim3(warpBlocks, 2), T>>>(x_human, x_object);
    k_zero_pools<<<(NB * DIM + T - 1) / T, T>>>();
    k_epool<<<(NE * 32 + T - 1) / T, T>>>(ei_ho, ea_ho, hbatch, W_emlp, b_emlp);

    for (int l = 0; l < NL; l++) {
        if (l > 0) k_gemm_mma<<<gemmGrid, 256, GSM_TOTAL>>>(l);
        // sequential relations: each launch's gather set (one hs side) fits L2
        k_edge<<<warpBlocks, T>>>(l, 0, bias_ho + l * DIM, obatch);
        k_edge<<<warpBlocks, T>>>(l, 1, bias_oh + l * DIM, hbatch);
    }

    k_final<<<NB, T>>>(W_p1, b_p1, W_p2, b_p2, out);
}

// round 17
// speedup vs baseline: 1.1789x; 1.0200x over previous
#include <cuda_runtime.h>
#include <cuda_bf16.h>
#include <cstdint>

#define NHN 50000
#define NON 50000
#define NMP 50048   // padded rows (391 * 128)
#define NE  500000
#define DIM 256
#define NL  8
#define NB  512
#define NC  117

// ---------------- device scratch (no allocations allowed) ----------------
__device__ float g_hs0[NHN * DIM];
__device__ float g_hs1[NON * DIM];
__device__ float g_as[2][2][NHN];   // [layer parity][rel]
__device__ float g_ad[2][2][NHN];   // [layer parity][rel]
__device__ float g_uv[4][NL * DIM];
__device__ float g_c[2 * NL * 2];

// bf16 hi/lo split node features (padded to NMP rows, zero-init pad).
__device__ __nv_bfloat16 g_xhh[NMP * DIM];
__device__ __nv_bfloat16 g_xhl[NMP * DIM];
__device__ __nv_bfloat16 g_xoh[NMP * DIM];
__device__ __nv_bfloat16 g_xol[NMP * DIM];

// W^T split: [rel*NL+l][n][k] bf16
__device__ __nv_bfloat16 g_Bh[2 * NL * DIM * DIM];
__device__ __nv_bfloat16 g_Bl[2 * NL * DIM * DIM];

__device__ int    g_cnt[2][NHN];
__device__ int    g_rowptr[2][NHN + 1];
__device__ int    g_pos[2][NHN];
__device__ int    g_srcP[2][NE];
__device__ float2 g_eaP[2][NE];

__device__ float g_hpool[NB * DIM];
__device__ float g_opool[NB * DIM];
__device__ float g_epool[NB * 32];
__device__ int   g_cnth[NB];
__device__ int   g_cnto[NB];
__device__ int   g_cnte[NB];

// ================= portable PTX helpers (sm_80+ features only) =============
__device__ __forceinline__ uint32_t smem_u32(const void* p) {
    uint32_t a;
    asm("{ .reg .u64 t; cvta.to.shared.u64 t, %1; cvt.u32.u64 %0, t; }"
        : "=r"(a) : "l"(p));
    return a;
}

__device__ __forceinline__ void cp16(uint32_t s, const void* g) {
    asm volatile("cp.async.cg.shared.global [%0], [%1], 16;" :: "r"(s), "l"(g) : "memory");
}

__device__ __forceinline__ void ldm4(uint32_t* r, uint32_t addr) {
    asm volatile("ldmatrix.sync.aligned.m8n8.x4.shared.b16 {%0,%1,%2,%3}, [%4];"
                 : "=r"(r[0]), "=r"(r[1]), "=r"(r[2]), "=r"(r[3]) : "r"(addr));
}

__device__ __forceinline__ void mma16816(float* c, const uint32_t* a, const uint32_t* b) {
    asm volatile(
        "mma.sync.aligned.m16n8k16.row.col.f32.bf16.bf16.f32 "
        "{%0,%1,%2,%3}, {%4,%5,%6,%7}, {%8,%9}, {%0,%1,%2,%3};"
        : "+f"(c[0]), "+f"(c[1]), "+f"(c[2]), "+f"(c[3])
        : "r"(a[0]), "r"(a[1]), "r"(a[2]), "r"(a[3]), "r"(b[0]), "r"(b[1]));
}

// ---------------- small kernels ----------------

__global__ void k_copy_x(const float* __restrict__ xh, const float* __restrict__ xo) {
    int i = blockIdx.x * blockDim.x + threadIdx.x;
    if (i < NHN * DIM) {
        float v = xh[i];
        __nv_bfloat16 h = __float2bfloat16(v);
        g_xhh[i] = h;
        g_xhl[i] = __float2bfloat16(v - __bfloat162float(h));
    }
    if (i < NON * DIM) {
        float v = xo[i];
        __nv_bfloat16 h = __float2bfloat16(v);
        g_xoh[i] = h;
        g_xol[i] = __float2bfloat16(v - __bfloat162float(h));
    }
}

// all four uv vectors in one launch; which = blockIdx.y
__global__ void k_matrow4(const float* __restrict__ W0, const float* __restrict__ a0,
                          const float* __restrict__ W1, const float* __restrict__ a1,
                          const float* __restrict__ W2, const float* __restrict__ a2,
                          const float* __restrict__ W3, const float* __restrict__ a3) {
    int which = blockIdx.y;
    const float* W = which == 0 ? W0 : which == 1 ? W1 : which == 2 ? W2 : W3;
    const float* a = which == 0 ? a0 : which == 1 ? a1 : which == 2 ? a2 : a3;
    int g = (blockIdx.x * blockDim.x + threadIdx.x) >> 5;
    if (g >= NL * DIM) return;
    int lane = threadIdx.x & 31;
    int l = g >> 8, i = g & 255;
    const float* wr = W + (size_t)l * DIM * DIM + (size_t)i * DIM;
    const float* ar = a + l * DIM;
    float s = 0.f;
    for (int j = lane; j < DIM; j += 32) s += wr[j] * ar[j];
#pragma unroll
    for (int off = 16; off > 0; off >>= 1) s += __shfl_down_sync(0xffffffffu, s, off);
    if (lane == 0) g_uv[which][g] = s;
}

// both relations' edge coefficients; rel = blockIdx.x
__global__ void k_cdot2(const float* __restrict__ We0, const float* __restrict__ ae0,
                        const float* __restrict__ We1, const float* __restrict__ ae1) {
    int rel = blockIdx.x;
    const float* We = rel ? We1 : We0;
    const float* ae = rel ? ae1 : ae0;
    int idx = threadIdx.x;
    if (idx >= NL * 2) return;
    int l = idx >> 1, k = idx & 1;
    const float* wr = We + (size_t)l * 2 * DIM + (size_t)k * DIM;
    const float* ar = ae + l * DIM;
    float s = 0.f;
    for (int j = 0; j < DIM; j++) s += wr[j] * ar[j];
    g_c[rel * NL * 2 + l * 2 + k] = s;
}

// W[l][k][n] -> Bh/Bl[(rel*NL+l)][n][k] (transpose + hi/lo split)
__global__ void k_prepW(const float* __restrict__ Wh, const float* __restrict__ Wo) {
    int idx = blockIdx.x * blockDim.x + threadIdx.x;
    if (idx >= 2 * NL * DIM * DIM) return;
    int rel = idx / (NL * DIM * DIM);
    int r = idx % (NL * DIM * DIM);
    int l = r / (DIM * DIM);
    int kk = (r / DIM) % DIM;
    int n = r % DIM;
    const float* W = rel ? Wo : Wh;
    float w = W[(size_t)l * DIM * DIM + (size_t)kk * DIM + n];
    __nv_bfloat16 hi = __float2bfloat16(w);
    __nv_bfloat16 lo = __float2bfloat16(w - __bfloat162float(hi));
    size_t dst = ((size_t)(rel * NL + l) * DIM + n) * DIM + kk;
    g_Bh[dst] = hi;
    g_Bl[dst] = lo;
}

__global__ void k_zero_csr() {
    int i = blockIdx.x * blockDim.x + threadIdx.x;
    if (i < NHN) { g_cnt[0][i] = 0; g_cnt[1][i] = 0; }
}

__global__ void k_hist2(const int* __restrict__ ei0, const int* __restrict__ ei1) {
    int rel = blockIdx.y;
    const int* ei = rel ? ei1 : ei0;
    int e = blockIdx.x * blockDim.x + threadIdx.x;
    if (e >= NE) return;
    atomicAdd(&g_cnt[rel][ei[NE + e]], 1);
}

__global__ void k_scan2() {
    int rel = blockIdx.x;
    __shared__ int part[1025];
    int T = blockDim.x, tid = threadIdx.x;
    int chunk = (NHN + T - 1) / T;
    int s0 = tid * chunk;
    int s1 = s0 + chunk; if (s1 > NHN) s1 = NHN;
    int s = 0;
    for (int i = s0; i < s1; i++) s += g_cnt[rel][i];
    part[tid] = s;
    __syncthreads();
    if (tid == 0) {
        int run = 0;
        for (int i = 0; i < T; i++) { int t = part[i]; part[i] = run; run += t; }
        part[T] = run;
    }
    __syncthreads();
    int run = part[tid];
    for (int i = s0; i < s1; i++) {
        g_rowptr[rel][i] = run;
        g_pos[rel][i] = run;
        run += g_cnt[rel][i];
    }
    if (tid == 0) g_rowptr[rel][NHN] = part[T];
}

__global__ void k_scatter2(const int* __restrict__ ei0, const float* __restrict__ ea0,
                           const int* __restrict__ ei1, const float* __restrict__ ea1) {
    int rel = blockIdx.y;
    const int* ei = rel ? ei1 : ei0;
    const float* ea = rel ? ea1 : ea0;
    int e = blockIdx.x * blockDim.x + threadIdx.x;
    if (e >= NE) return;
    int d = ei[NE + e];
    int p = atomicAdd(&g_pos[rel][d], 1);
    g_srcP[rel][p] = ei[e];
    g_eaP[rel][p] = ((const float2*)ea)[e];
}

// ============ mma.sync bf16 3-term split GEMM: C[50048,256] = A @ W ========
// BM=128, BN=128, BK=32, 256 thr (8 warps 2x4), warp tile 64x32.
// 2-stage cp.async double buffer; 2 CTAs/SM. sel passed as arg (per-stream).
#define GSM_STAGE 40960
#define GSM_TOTAL 81920

__global__ void __launch_bounds__(256, 2) k_gemm_mma(int l, int sel) {
    extern __shared__ char smem[];
    const __nv_bfloat16* Agh = sel ? g_xoh : g_xhh;
    const __nv_bfloat16* Agl = sel ? g_xol : g_xhl;
    const __nv_bfloat16* Bgh = g_Bh + (size_t)(sel * NL + l) * DIM * DIM;
    const __nv_bfloat16* Bgl = g_Bl + (size_t)(sel * NL + l) * DIM * DIM;
    float* Cm = sel ? g_hs1 : g_hs0;

    int tid = threadIdx.x, lane = tid & 31, wid = tid >> 5;
    int warpM = wid & 1, warpN = wid >> 1;
    int rowBase = blockIdx.x * 128;
    int colBase = blockIdx.y * 128;
    uint32_t sb = smem_u32(smem);

    float acc[16][4];
#pragma unroll
    for (int i = 0; i < 16; i++)
#pragma unroll
        for (int j = 0; j < 4; j++) acc[i][j] = 0.f;

    int c0 = tid * 2;
    int rA0 = (c0) >> 2, kch0 = (c0) & 3;
    int rA1 = (c0 + 1) >> 2, kch1 = (c0 + 1) & 3;

    int rowA = (lane & 7) + 8 * ((lane >> 3) & 1);
    int chA = lane >> 4;
    int rowB = (lane & 7) + 8 * (lane >> 4);
    int chB = (lane >> 3) & 1;

#define LOAD_STAGE(kc, stg) do {                                              \
    uint32_t stb = sb + (stg) * GSM_STAGE;                                    \
    size_t ga0 = ((size_t)(rowBase + rA0)) * DIM + (kc) * 32 + kch0 * 8;      \
    size_t ga1 = ((size_t)(rowBase + rA1)) * DIM + (kc) * 32 + kch1 * 8;      \
    size_t gb0 = ((size_t)(colBase + rA0)) * DIM + (kc) * 32 + kch0 * 8;      \
    size_t gb1 = ((size_t)(colBase + rA1)) * DIM + (kc) * 32 + kch1 * 8;      \
    uint32_t d0 = stb + rA0 * 80 + kch0 * 16;                                 \
    uint32_t d1 = stb + rA1 * 80 + kch1 * 16;                                 \
    cp16(d0, Agh + ga0);          cp16(d1, Agh + ga1);                        \
    cp16(d0 + 10240, Agl + ga0);  cp16(d1 + 10240, Agl + ga1);                \
    cp16(d0 + 20480, Bgh + gb0);  cp16(d1 + 20480, Bgh + gb1);                \
    cp16(d0 + 30720, Bgl + gb0);  cp16(d1 + 30720, Bgl + gb1);                \
    asm volatile("cp.async.commit_group;" ::: "memory");                      \
} while (0)

    LOAD_STAGE(0, 0);

#pragma unroll 1
    for (int kc = 0; kc < 8; kc++) {
        if (kc < 7) {
            LOAD_STAGE(kc + 1, (kc + 1) & 1);
            asm volatile("cp.async.wait_group 1;" ::: "memory");
        } else {
            asm volatile("cp.async.wait_group 0;" ::: "memory");
        }
        __syncthreads();

        uint32_t stb = sb + (kc & 1) * GSM_STAGE;
#pragma unroll
        for (int k16 = 0; k16 < 2; k16++) {
            uint32_t kb = k16 * 32;
            uint32_t fah[4][4], fal[4][4];
#pragma unroll
            for (int i = 0; i < 4; i++) {
                uint32_t a = stb + (uint32_t)(warpM * 64 + i * 16 + rowA) * 80 + kb + chA * 16;
                ldm4(fah[i], a);
                ldm4(fal[i], a + 10240);
            }
            uint32_t fbh[4][2], fbl[4][2];
#pragma unroll
            for (int j = 0; j < 2; j++) {
                uint32_t a = stb + 20480 + (uint32_t)(warpN * 32 + j * 16 + rowB) * 80 + kb + chB * 16;
                uint32_t t[4];
                ldm4(t, a);
                fbh[2 * j][0] = t[0]; fbh[2 * j][1] = t[1];
                fbh[2 * j + 1][0] = t[2]; fbh[2 * j + 1][1] = t[3];
                ldm4(t, a + 10240);
                fbl[2 * j][0] = t[0]; fbl[2 * j][1] = t[1];
                fbl[2 * j + 1][0] = t[2]; fbl[2 * j + 1][1] = t[3];
            }
#pragma unroll
            for (int i = 0; i < 4; i++)
#pragma unroll
                for (int j = 0; j < 4; j++) {
                    mma16816(acc[i * 4 + j], fah[i], fbh[j]);
                    mma16816(acc[i * 4 + j], fah[i], fbl[j]);
                    mma16816(acc[i * 4 + j], fal[i], fbh[j]);
                }
        }
        __syncthreads();
    }

#pragma unroll
    for (int i = 0; i < 4; i++) {
        int r0 = rowBase + warpM * 64 + i * 16 + (lane >> 2);
#pragma unroll
        for (int j = 0; j < 4; j++) {
            int c = colBase + warpN * 32 + j * 8 + 2 * (lane & 3);
            float* cp = Cm + (size_t)r0 * DIM + c;
            if (r0 < NHN) *(float2*)cp = make_float2(acc[i * 4 + j][0], acc[i * 4 + j][1]);
            if (r0 + 8 < NHN)
                *(float2*)(cp + 8 * DIM) = make_float2(acc[i * 4 + j][2], acc[i * 4 + j][3]);
        }
    }
}

// initial a_s/a_d (layer 0) straight from input tensors; sel = blockIdx.y
__global__ void k_attn0(const float* __restrict__ xh, const float* __restrict__ xo) {
    int sel = blockIdx.y;
    int w = (blockIdx.x * blockDim.x + threadIdx.x) >> 5;
    if (w >= NHN) return;
    int lane = threadIdx.x & 31;
    const float* x = sel ? xo : xh;
    const float* u = sel ? &g_uv[2][0] : &g_uv[0][0];
    const float* v = sel ? &g_uv[1][0] : &g_uv[3][0];
    float* as_out = sel ? g_as[0][1] : g_as[0][0];
    float* ad_out = sel ? g_ad[0][0] : g_ad[0][1];
    const float4* xr = (const float4*)&x[(size_t)w * DIM];
    float4 x0 = xr[lane * 2], x1 = xr[lane * 2 + 1];
    const float4* ur = (const float4*)u;
    const float4* vr = (const float4*)v;
    float4 u0 = ur[lane * 2], u1 = ur[lane * 2 + 1];
    float4 v0 = vr[lane * 2], v1 = vr[lane * 2 + 1];
    float su = x0.x * u0.x + x0.y * u0.y + x0.z * u0.z + x0.w * u0.w +
               x1.x * u1.x + x1.y * u1.y + x1.z * u1.z + x1.w * u1.w;
    float sv = x0.x * v0.x + x0.y * v0.y + x0.z * v0.z + x0.w * v0.w +
               x1.x * v1.x + x1.y * v1.y + x1.z * v1.z + x1.w * v1.w;
#pragma unroll
    for (int off = 16; off > 0; off >>= 1) {
        su += __shfl_down_sync(0xffffffffu, su, off);
        sv += __shfl_down_sync(0xffffffffu, sv, off);
    }
    if (lane == 0) { as_out[w] = su; ad_out[w] = sv; }
}

// ===== fused per-layer edge kernel (R14 register version; one relation/launch)
__global__ void k_edge(int l, int rel, const float* __restrict__ bias_l,
                       const int* __restrict__ batch) {
    int w = (blockIdx.x * blockDim.x + threadIdx.x) >> 5;
    if (w >= NHN) return;
    int lane = threadIdx.x & 31;
    int buf = l & 1;
    int lastLayer = (l == NL - 1);
    const float* hs = rel ? g_hs1 : g_hs0;
    __nv_bfloat16* xhh = rel ? g_xhh : g_xoh;   // dst-side feature hi
    __nv_bfloat16* xhl = rel ? g_xhl : g_xol;
    const float c0 = g_c[rel * NL * 2 + l * 2 + 0];
    const float c1 = g_c[rel * NL * 2 + l * 2 + 1];
    const float* __restrict__ asv = g_as[buf][rel];
    const float ad = g_ad[buf][rel][w];
    const int* __restrict__ srcP = g_srcP[rel];
    int s0 = g_rowptr[rel][w], s1 = g_rowptr[rel][w + 1];
    int deg = s1 - s0;
    int col = lane * 8;

    // pass 1: online softmax stats (per-lane, then warp merge); cache <=8 slots
    float m = -3.4e38f, den = 0.f;
    int lsrc[8] = {0, 0, 0, 0, 0, 0, 0, 0};
    float llg[8] = {0.f, 0.f, 0.f, 0.f, 0.f, 0.f, 0.f, 0.f};
#pragma unroll
    for (int slot = 0; slot < 8; slot++) {
        int p = s0 + slot * 32 + lane;
        if (p < s1) {
            int s = srcP[p];
            float2 ea = g_eaP[rel][p];
            float lg = asv[s] + ad + ea.x * c0 + ea.y * c1;
            lg = lg > 0.f ? lg : 0.2f * lg;
            lsrc[slot] = s; llg[slot] = lg;
            float mn = fmaxf(m, lg);
            den = den * __expf(m - mn) + __expf(lg - mn);
            m = mn;
        }
    }
    for (int p = s0 + 256 + lane; p < s1; p += 32) {  // overflow (deg>256), ~never
        int s = srcP[p];
        float2 ea = g_eaP[rel][p];
        float lg = asv[s] + ad + ea.x * c0 + ea.y * c1;
        lg = lg > 0.f ? lg : 0.2f * lg;
        float mn = fmaxf(m, lg);
        den = den * __expf(m - mn) + __expf(lg - mn);
        m = mn;
    }
#pragma unroll
    for (int off = 16; off > 0; off >>= 1) {
        float m2 = __shfl_xor_sync(0xffffffffu, m, off);
        float d2 = __shfl_xor_sync(0xffffffffu, den, off);
        float mn = fmaxf(m, m2);
        den = den * __expf(m - mn) + d2 * __expf(m2 - mn);
        m = mn;
    }
    float inv = deg > 0 ? 1.f / den : 0.f;

    // pass 2: weighted aggregation (2 edges in flight)
    float acc[8] = {0.f, 0.f, 0.f, 0.f, 0.f, 0.f, 0.f, 0.f};
#pragma unroll
    for (int slot = 0; slot < 8; slot++) {
        int base = s0 + slot * 32;
        if (base < s1) {
            int cnt = min(32, s1 - base);
            float alOwn = (lane < cnt) ? __expf(llg[slot] - m) * inv : 0.f;
            int srcOwn = lsrc[slot];
            int j = 0;
            for (; j + 1 < cnt; j += 2) {
                float alA = __shfl_sync(0xffffffffu, alOwn, j);
                int sA = __shfl_sync(0xffffffffu, srcOwn, j);
                float alB = __shfl_sync(0xffffffffu, alOwn, j + 1);
                int sB = __shfl_sync(0xffffffffu, srcOwn, j + 1);
                const float4* hpA = (const float4*)&hs[(size_t)sA * DIM + col];
                const float4* hpB = (const float4*)&hs[(size_t)sB * DIM + col];
                float4 a0 = hpA[0], a1 = hpA[1];
                float4 b0 = hpB[0], b1 = hpB[1];
                acc[0] += alA * a0.x + alB * b0.x; acc[1] += alA * a0.y + alB * b0.y;
                acc[2] += alA * a0.z + alB * b0.z; acc[3] += alA * a0.w + alB * b0.w;
                acc[4] += alA * a1.x + alB * b1.x; acc[5] += alA * a1.y + alB * b1.y;
                acc[6] += alA * a1.z + alB * b1.z; acc[7] += alA * a1.w + alB * b1.w;
            }
            if (j < cnt) {
                float al = __shfl_sync(0xffffffffu, alOwn, j);
                int s = __shfl_sync(0xffffffffu, srcOwn, j);
                const float4* hp = (const float4*)&hs[(size_t)s * DIM + col];
                float4 h0 = hp[0], h1 = hp[1];
                acc[0] += al * h0.x; acc[1] += al * h0.y;
                acc[2] += al * h0.z; acc[3] += al * h0.w;
                acc[4] += al * h1.x; acc[5] += al * h1.y;
                acc[6] += al * h1.z; acc[7] += al * h1.w;
            }
        }
    }
    for (int p = s0 + 256; p < s1; p++) {  // overflow path, ~never
        int s = srcP[p];
        float2 ea = g_eaP[rel][p];
        float lg = asv[s] + ad + ea.x * c0 + ea.y * c1;
        lg = lg > 0.f ? lg : 0.2f * lg;
        float al = __expf(lg - m) * inv;
        const float4* hp = (const float4*)&hs[(size_t)s * DIM + col];
        float4 h0 = hp[0], h1 = hp[1];
        acc[0] += al * h0.x; acc[1] += al * h0.y;
        acc[2] += al * h0.z; acc[3] += al * h0.w;
        acc[4] += al * h1.x; acc[5] += al * h1.y;
        acc[6] += al * h1.z; acc[7] += al * h1.w;
    }

    // epilogue: bias + relu + residual (residual from bf16 hi/lo pair)
    float4 b0 = *(const float4*)&bias_l[col];
    float4 b1 = *(const float4*)&bias_l[col + 4];
    float o[8];
    o[0] = fmaxf(acc[0] + b0.x, 0.f); o[1] = fmaxf(acc[1] + b0.y, 0.f);
    o[2] = fmaxf(acc[2] + b0.z, 0.f); o[3] = fmaxf(acc[3] + b0.w, 0.f);
    o[4] = fmaxf(acc[4] + b1.x, 0.f); o[5] = fmaxf(acc[5] + b1.y, 0.f);
    o[6] = fmaxf(acc[6] + b1.z, 0.f); o[7] = fmaxf(acc[7] + b1.w, 0.f);
    size_t xoff = (size_t)w * DIM + col;
    if (l > 0) {
        union { uint4 u; __nv_bfloat16 h[8]; } rh, rl;
        rh.u = *(const uint4*)&xhh[xoff];
        rl.u = *(const uint4*)&xhl[xoff];
#pragma unroll
        for (int j = 0; j < 8; j++)
            o[j] += __bfloat162float(rh.h[j]) + __bfloat162float(rl.h[j]);
    }

    if (!lastLayer) {
        union { uint4 u; __nv_bfloat16 h[8]; } ph, pl;
#pragma unroll
        for (int j = 0; j < 8; j++) {
            __nv_bfloat16 h = __float2bfloat16(o[j]);
            ph.h[j] = h;
            pl.h[j] = __float2bfloat16(o[j] - __bfloat162float(h));
        }
        *(uint4*)&xhh[xoff] = ph.u;
        *(uint4*)&xhl[xoff] = pl.u;
        // next layer's attention scalars from registers
        const float* u = rel ? &g_uv[0][(l + 1) * DIM] : &g_uv[2][(l + 1) * DIM];
        const float* v = rel ? &g_uv[3][(l + 1) * DIM] : &g_uv[1][(l + 1) * DIM];
        float su = 0.f, sv = 0.f;
#pragma unroll
        for (int j = 0; j < 8; j++) {
            su += o[j] * u[col + j];
            sv += o[j] * v[col + j];
        }
#pragma unroll
        for (int off = 16; off > 0; off >>= 1) {
            su += __shfl_down_sync(0xffffffffu, su, off);
            sv += __shfl_down_sync(0xffffffffu, sv, off);
        }
        if (lane == 0) {
            int nbuf = buf ^ 1;
            (rel ? g_as[nbuf][0] : g_as[nbuf][1])[w] = su;
            (rel ? g_ad[nbuf][1] : g_ad[nbuf][0])[w] = sv;
        }
    } else {
        // final layer: pool directly (mean over batch segments)
        float* pool = rel ? g_hpool : g_opool;
        int* cnt = rel ? g_cnth : g_cnto;
        int b = batch[w];
        float* pr = &pool[b * DIM + col];
        atomicAdd(pr + 0, o[0]); atomicAdd(pr + 1, o[1]);
        atomicAdd(pr + 2, o[2]); atomicAdd(pr + 3, o[3]);
        atomicAdd(pr + 4, o[4]); atomicAdd(pr + 5, o[5]);
        atomicAdd(pr + 6, o[6]); atomicAdd(pr + 7, o[7]);
        if (lane == 0) atomicAdd(&cnt[b], 1);
    }
}

__global__ void k_zero_pools() {
    int i = blockIdx.x * blockDim.x + threadIdx.x;
    if (i < NB * DIM) { g_hpool[i] = 0.f; g_opool[i] = 0.f; }
    if (i < NB * 32) g_epool[i] = 0.f;
    if (i < NB) { g_cnth[i] = 0; g_cnto[i] = 0; g_cnte[i] = 0; }
}

__global__ void k_epool(const int* __restrict__ ei, const float* __restrict__ ea,
                        const int* __restrict__ hbatch,
                        const float* __restrict__ Wm, const float* __restrict__ bm) {
    int e = (blockIdx.x * blockDim.x + threadIdx.x) >> 5;
    if (e >= NE) return;
    int lane = threadIdx.x & 31;
    int src = ei[e];
    int b = hbatch[src];
    float2 eav = ((const float2*)ea)[e];
    float val = eav.x * Wm[lane] + eav.y * Wm[32 + lane] + bm[lane];
    val = fmaxf(val, 0.f);
    atomicAdd(&g_epool[b * 32 + lane], val);
    if (lane == 0) atomicAdd(&g_cnte[b], 1);
}

__global__ void k_final(const float* __restrict__ Wp1, const float* __restrict__ bp1,
                        const float* __restrict__ Wp2, const float* __restrict__ bp2,
                        float* __restrict__ out) {
    __shared__ float emb[544];
    __shared__ float logits[240];
    __shared__ float mred[2], sred[2];
    int b = blockIdx.x, t = threadIdx.x;
    float ch = fmaxf((float)g_cnth[b], 1.f);
    float co = fmaxf((float)g_cnto[b], 1.f);
    float ce = fmaxf((float)g_cnte[b], 1.f);
    emb[t] = g_hpool[b * DIM + t] / ch;
    emb[256 + t] = g_opool[b * DIM + t] / co;
    if (t < 32) emb[512 + t] = g_epool[b * 32 + t] / ce;
    __syncthreads();
    if (t < 2 * NC) {
        int head = (t < NC) ? 0 : 1;
        int c = head ? (t - NC) : t;
        const float* W = head ? Wp2 : Wp1;
        const float* bb = head ? bp2 : bp1;
        float s = bb[c];
        for (int k = 0; k < 544; k++) s += emb[k] * W[k * NC + c];
        logits[t] = s;
    }
    __syncthreads();
    if (t < 2) {
        float m = -3.4e38f;
        for (int i = 0; i < NC; i++) m = fmaxf(m, logits[t * NC + i]);
        float sum = 0.f;
        for (int i = 0; i < NC; i++) sum += expf(logits[t * NC + i] - m);
        mred[t] = m; sred[t] = sum;
    }
    __syncthreads();
    if (t < 2 * NC) {
        int head = (t < NC) ? 0 : 1;
        out[(size_t)b * 2 * NC + t] = expf(logits[t] - mred[head]) / sred[head];
    }
}

// ---------------- launch ----------------
extern "C" void kernel_launch(void* const* d_in, const int* in_sizes, int n_in,
                              void* d_out, int out_size) {
    const float* x_human = (const float*)d_in[0];
    const float* x_object = (const float*)d_in[1];
    const int* ei_ho = (const int*)d_in[2];
    const int* ei_oh = (const int*)d_in[3];
    const float* ea_ho = (const float*)d_in[4];
    const float* ea_oh = (const float*)d_in[5];
    const int* hbatch = (const int*)d_in[6];
    const int* obatch = (const int*)d_in[7];
    const float* Wsrc_ho = (const float*)d_in[8];
    const float* Wdst_ho = (const float*)d_in[9];
    const float* asrc_ho = (const float*)d_in[10];
    const float* adst_ho = (const float*)d_in[11];
    const float* Wedge_ho = (const float*)d_in[12];
    const float* aedge_ho = (const float*)d_in[13];
    const float* bias_ho = (const float*)d_in[14];
    const float* Wsrc_oh = (const float*)d_in[15];
    const float* Wdst_oh = (const float*)d_in[16];
    const float* asrc_oh = (const float*)d_in[17];
    const float* adst_oh = (const float*)d_in[18];
    const float* Wedge_oh = (const float*)d_in[19];
    const float* aedge_oh = (const float*)d_in[20];
    const float* bias_oh = (const float*)d_in[21];
    const float* W_emlp = (const float*)d_in[22];
    const float* b_emlp = (const float*)d_in[23];
    const float* W_p1 = (const float*)d_in[24];
    const float* b_p1 = (const float*)d_in[25];
    const float* W_p2 = (const float*)d_in[26];
    const float* b_p2 = (const float*)d_in[27];
    float* out = (float*)d_out;

    // one-time stream/event setup (first call is the uncaptured correctness run)
    static cudaStream_t sB = nullptr;
    static cudaEvent_t evFork;
    static cudaEvent_t evAg[NL], evAe[NL], evBg[NL], evBe[NL];
    if (!sB) {
        cudaStreamCreateWithFlags(&sB, cudaStreamNonBlocking);
        cudaEventCreateWithFlags(&evFork, cudaEventDisableTiming);
        for (int l = 0; l < NL; l++) {
            cudaEventCreateWithFlags(&evAg[l], cudaEventDisableTiming);
            cudaEventCreateWithFlags(&evAe[l], cudaEventDisableTiming);
            cudaEventCreateWithFlags(&evBg[l], cudaEventDisableTiming);
            cudaEventCreateWithFlags(&evBe[l], cudaEventDisableTiming);
        }
        cudaFuncSetAttribute(k_gemm_mma, cudaFuncAttributeMaxDynamicSharedMemorySize,
                             GSM_TOTAL);
    }

    const int T = 256;
    dim3 gemmGrid(NMP / 128, DIM / 128, 1);   // (391, 2) per side
    int warpBlocks = (NHN * 32 + T - 1) / T;
    int neBlocks = (NE + T - 1) / T;

    // ---- prep (default stream) ----
    k_copy_x<<<(NHN * DIM + T - 1) / T, T>>>(x_human, x_object);
    k_prepW<<<(2 * NL * DIM * DIM + T - 1) / T, T>>>(Wsrc_ho, Wsrc_oh);
    k_zero_csr<<<(NHN + T - 1) / T, T>>>();
    k_hist2<<<dim3(neBlocks, 2), T>>>(ei_ho, ei_oh);
    k_scan2<<<2, 1024>>>();
    k_scatter2<<<dim3(neBlocks, 2), T>>>(ei_ho, ea_ho, ei_oh, ea_oh);
    k_matrow4<<<dim3((NL * DIM * 32 + T - 1) / T, 4), T>>>(
        Wsrc_ho, asrc_ho, Wdst_ho, adst_ho, Wsrc_oh, asrc_oh, Wdst_oh, adst_oh);
    k_cdot2<<<2, 32>>>(Wedge_ho, aedge_ho, Wedge_oh, aedge_oh);
    k_attn0<<<dim3(warpBlocks, 2), T>>>(x_human, x_object);
    k_zero_pools<<<(NB * DIM + T - 1) / T, T>>>();
    k_epool<<<(NE * 32 + T - 1) / T, T>>>(ei_ho, ea_ho, hbatch, W_emlp, b_emlp);

    // ---- fork stream B ----
    cudaEventRecord(evFork, 0);
    cudaStreamWaitEvent(sB, evFork, 0);

    // ---- pipelined layers: A = (g0, e0) on default; B = (g1, e1) on sB ----
    for (int l = 0; l < NL; l++) {
        // A: gemm humans
        if (l > 0) cudaStreamWaitEvent(0, evBe[l - 1], 0);
        k_gemm_mma<<<gemmGrid, 256, GSM_TOTAL, 0>>>(l, 0);
        cudaEventRecord(evAg[l], 0);
        // B: gemm objects
        if (l > 0) cudaStreamWaitEvent(sB, evAe[l - 1], 0);
        k_gemm_mma<<<gemmGrid, 256, GSM_TOTAL, sB>>>(l, 1);
        cudaEventRecord(evBg[l], sB);
        // A: edge rel0 (reads hs0, writes x_objects) — must follow g1 (WAR on x_o)
        cudaStreamWaitEvent(0, evBg[l], 0);
        k_edge<<<warpBlocks, T, 0, 0>>>(l, 0, bias_ho + l * DIM, obatch);
        cudaEventRecord(evAe[l], 0);
        // B: edge rel1 (reads hs1, writes x_humans) — must follow g0 (WAR on x_h)
        cudaStreamWaitEvent(sB, evAg[l], 0);
        k_edge<<<warpBlocks, T, 0, sB>>>(l, 1, bias_oh + l * DIM, hbatch);
        cudaEventRecord(evBe[l], sB);
    }

    // ---- join ----
    cudaStreamWaitEvent(0, evBe[NL - 1], 0);
    k_final<<<NB, T>>>(W_p1, b_p1, W_p2, b_p2, out);
}